// round 15
// baseline (speedup 1.0000x reference)
#include <cuda_runtime.h>
#include <math_constants.h>
#include <float.h>

// SMPL NN skinning — Morton-sorted verts AND points; per-thread pruned exact
// search; vert table + bounds + lists ALL in shared memory; 512-thr CTA.
//  seed: evaluate 3 groups at vstart[cell(p)]>>3 (exact d2) -> ub2
//  B1/B2: packed-f32x2 sphere tests, dummy-slot branch-free compaction
//  C: exact bit-identical reference d2 on candidate groups, lex (d2,idx) min
// Output: [0,3n) x_bar | [3n,12n) rotation_bar | [12n,28n) T_fwd

typedef unsigned long long ull;

__device__ __forceinline__ ull f2_mul(ull a, ull b) {
    ull r; asm("mul.rn.f32x2 %0,%1,%2;" : "=l"(r) : "l"(a), "l"(b)); return r;
}
__device__ __forceinline__ ull f2_fma(ull a, ull b, ull c) {
    ull r; asm("fma.rn.f32x2 %0,%1,%2,%3;" : "=l"(r) : "l"(a), "l"(b), "l"(c)); return r;
}
__device__ __forceinline__ ull f2_add(ull a, ull b) {
    ull r; asm("add.rn.f32x2 %0,%1,%2;" : "=l"(r) : "l"(a), "l"(b)); return r;
}
__device__ __forceinline__ ull f2_pack(float lo, float hi) {
    ull r; asm("mov.b64 %0,{%1,%2};" : "=l"(r) : "f"(lo), "f"(hi)); return r;
}
__device__ __forceinline__ float2 f2_unpack(ull v) {
    float lo, hi; asm("mov.b64 {%0,%1},%2;" : "=f"(lo), "=f"(hi) : "l"(v));
    return make_float2(lo, hi);
}

static constexpr int   NC     = 16;
static constexpr int   NCELLS = NC * NC * NC;     // 4096
static constexpr float ORG    = -4.0f;
static constexpr float INV_CS = 2.0f;
static constexpr int   MAXN   = 100000;
static constexpr int   MAXVP  = 6896;             // mult of 16
static constexpr int   NPAIRS = MAXVP / 2;
static constexpr int   NGRP   = MAXVP / 8;        // 862
static constexpr int   NSUPP  = 108;
static constexpr int   NSP    = NSUPP / 2;        // 54
static constexpr int   NGPP   = NSUPP * 4;        // 432 group-pairs (padded)
static constexpr int   SCAP   = 16;
static constexpr int   GCAP   = 64;
static constexpr int   NTHR   = 512;              // one CTA/SM, 16 warps

// vert side
__device__ int    g_vcount[NCELLS];
__device__ int    g_vstart[NCELLS + 1];
__device__ int    g_vrank[MAXVP];
__device__ int    g_vcellid[MAXVP];
__device__ float4 g_vs[MAXVP];
__device__ int    g_vidx[MAXVP];
__device__ float4 g_vp[MAXVP];                    // pair-packed verts
__device__ unsigned short g_vidx16[MAXVP];
__device__ float4 g_gpA[NGPP], g_gpB[NGPP];
__device__ float4 g_spA[NSP], g_spB[NSP];
// point side
__device__ int    g_pcount[NCELLS];
__device__ int    g_pstart[NCELLS + 1];
__device__ int    g_prank[MAXN];
__device__ int    g_pcellid[MAXN];
__device__ int    g_order[MAXN];

__device__ __forceinline__ int cell_coord(float x) {
    int c = (int)floorf((x - ORG) * INV_CS);
    return min(NC - 1, max(0, c));
}
__device__ __forceinline__ int spread4(int v) {
    return (v & 1) | ((v & 2) << 2) | ((v & 4) << 4) | ((v & 8) << 6);
}
__device__ __forceinline__ int morton_cell(float x, float y, float z) {
    return spread4(cell_coord(x)) | (spread4(cell_coord(y)) << 1)
         | (spread4(cell_coord(z)) << 2);
}

// ───────────── build kernels ─────────────
__global__ void zero_counts(int nv) {
    int i = blockIdx.x * blockDim.x + threadIdx.x;   // 4096
    if (i < NCELLS) { g_vcount[i] = 0; g_pcount[i] = 0; }
    for (int k = nv + i; k < MAXVP; k += NCELLS) {
        g_vs[k]   = make_float4(1e7f, 1e7f, 1e7f, CUDART_INF_F);
        g_vidx[k] = 0xFFFF;
    }
}

__global__ void count_kernel(const float* __restrict__ verts,
                             const float* __restrict__ xyz, int nv, int n) {
    int i = blockIdx.x * blockDim.x + threadIdx.x;
    if (i < nv) {
        int cid = morton_cell(verts[3 * i], verts[3 * i + 1], verts[3 * i + 2]);
        g_vcellid[i] = cid;
        g_vrank[i] = atomicAdd(&g_vcount[cid], 1);
    }
    if (i < n) {
        int cid = morton_cell(xyz[3 * i], xyz[3 * i + 1], xyz[3 * i + 2]);
        g_pcellid[i] = cid;
        g_prank[i] = atomicAdd(&g_pcount[cid], 1);
    }
}

__global__ void __launch_bounds__(1024) scan_offsets() {
    __shared__ int part[1024];
    const int t = threadIdx.x;
    int* cnt = blockIdx.x ? g_pcount : g_vcount;
    int* st  = blockIdx.x ? g_pstart : g_vstart;
    const int CHUNK = NCELLS / 1024;   // 4
    int base = t * CHUNK, s = 0;
    #pragma unroll
    for (int k = 0; k < CHUNK; ++k) s += cnt[base + k];
    part[t] = s;
    __syncthreads();
    for (int off = 1; off < 1024; off <<= 1) {
        int v = (t >= off) ? part[t - off] : 0;
        __syncthreads(); part[t] += v; __syncthreads();
    }
    int excl = part[t] - s;
    #pragma unroll
    for (int k = 0; k < CHUNK; ++k) { st[base + k] = excl; excl += cnt[base + k]; }
    if (t == 1023) st[NCELLS] = part[1023];
}

__global__ void scatter_kernel(const float* __restrict__ verts, int nv, int n) {
    int i = blockIdx.x * blockDim.x + threadIdx.x;
    if (i < nv) {
        float x = verts[3 * i], y = verts[3 * i + 1], z = verts[3 * i + 2];
        float sv = __fadd_rn(__fadd_rn(__fmul_rn(x, x), __fmul_rn(y, y)),
                             __fmul_rn(z, z));
        int pos = g_vstart[g_vcellid[i]] + g_vrank[i];
        g_vs[pos]   = make_float4(x, y, z, sv);
        g_vidx[pos] = i;
    }
    if (i < n) g_order[g_pstart[g_pcellid[i]] + g_prank[i]] = i;
}

__global__ void __launch_bounds__(1024) bounds_kernel(int nv) {
    __shared__ float4 sgb[NGRP];
    __shared__ float4 ssb[NSUPP];
    const int tid = threadIdx.x;

    for (int g = tid; g < NGRP; g += 1024) {
        float mnx = FLT_MAX, mny = FLT_MAX, mnz = FLT_MAX;
        float mxx = -FLT_MAX, mxy = -FLT_MAX, mxz = -FLT_MAX;
        bool any = false;
        #pragma unroll
        for (int k = 0; k < 8; ++k) {
            float4 v = g_vs[g * 8 + k];
            if (isinf(v.w)) continue;
            any = true;
            mnx = fminf(mnx, v.x); mxx = fmaxf(mxx, v.x);
            mny = fminf(mny, v.y); mxy = fmaxf(mxy, v.y);
            mnz = fminf(mnz, v.z); mxz = fmaxf(mxz, v.z);
        }
        float4 b;
        if (!any) {
            b = make_float4(1e7f, 1e7f, 1e7f, 0.f);
        } else {
            float cx = 0.5f * (mnx + mxx), cy = 0.5f * (mny + mxy), cz = 0.5f * (mnz + mxz);
            float m2 = 0.f;
            #pragma unroll
            for (int k = 0; k < 8; ++k) {
                float4 v = g_vs[g * 8 + k];
                if (isinf(v.w)) continue;
                float dx = v.x - cx, dy = v.y - cy, dz = v.z - cz;
                m2 = fmaxf(m2, dx * dx + dy * dy + dz * dz);
            }
            b = make_float4(cx, cy, cz, sqrtf(m2) * 1.0002f + 1e-5f);
        }
        sgb[g] = b;
    }
    __syncthreads();

    if (tid < NSUPP) {
        float mnx = FLT_MAX, mny = FLT_MAX, mnz = FLT_MAX;
        float mxx = -FLT_MAX, mxy = -FLT_MAX, mxz = -FLT_MAX;
        bool any = false;
        for (int k = 0; k < 8; ++k) {
            int g = tid * 8 + k;
            if (g >= NGRP) break;
            float4 b = sgb[g];
            if (b.x > 9e6f) continue;
            any = true;
            mnx = fminf(mnx, b.x - b.w); mxx = fmaxf(mxx, b.x + b.w);
            mny = fminf(mny, b.y - b.w); mxy = fmaxf(mxy, b.y + b.w);
            mnz = fminf(mnz, b.z - b.w); mxz = fmaxf(mxz, b.z + b.w);
        }
        if (!any) {
            ssb[tid] = make_float4(1e7f, 1e7f, 1e7f, 0.f);
        } else {
            float cx = 0.5f * (mnx + mxx), cy = 0.5f * (mny + mxy), cz = 0.5f * (mnz + mxz);
            float mr = 0.f;
            for (int k = 0; k < 8; ++k) {
                int g = tid * 8 + k;
                if (g >= NGRP) break;
                float4 b = sgb[g];
                if (b.x > 9e6f) continue;
                float dx = b.x - cx, dy = b.y - cy, dz = b.z - cz;
                mr = fmaxf(mr, sqrtf(dx * dx + dy * dy + dz * dz) + b.w);
            }
            ssb[tid] = make_float4(cx, cy, cz, mr * 1.0002f + 1e-5f);
        }
    }
    __syncthreads();

    for (int p = tid; p < NPAIRS; p += 1024) {
        float4 v0 = g_vs[2 * p], v1 = g_vs[2 * p + 1];
        g_vp[2 * p]     = make_float4(v0.x, v1.x, v0.y, v1.y);
        g_vp[2 * p + 1] = make_float4(v0.z, v1.z, v0.w, v1.w);
        g_vidx16[2 * p]     = (unsigned short)g_vidx[2 * p];
        g_vidx16[2 * p + 1] = (unsigned short)g_vidx[2 * p + 1];
    }
    for (int gp = tid; gp < NGPP; gp += 1024) {
        int g0 = 2 * gp, g1 = 2 * gp + 1;
        float4 b0 = (g0 < NGRP) ? sgb[g0] : make_float4(1e7f, 1e7f, 1e7f, 0.f);
        float4 b1 = (g1 < NGRP) ? sgb[g1] : make_float4(1e7f, 1e7f, 1e7f, 0.f);
        g_gpA[gp] = make_float4(b0.x, b1.x, b0.y, b1.y);
        g_gpB[gp] = make_float4(b0.z, b1.z, b0.w, b1.w);
    }
    if (tid < NSP) {
        float4 b0 = ssb[2 * tid], b1 = ssb[2 * tid + 1];
        g_spA[tid] = make_float4(b0.x, b1.x, b0.y, b1.y);
        g_spB[tid] = make_float4(b0.z, b1.z, b0.w, b1.w);
    }
}

// ─────────── NN + skinning (512 threads, all-smem) ───────────
static constexpr int SVP_OFF   = 0;                         // float4[MAXVP] 110336
static constexpr int SVIDX_OFF = SVP_OFF + MAXVP * 16;      // u16[MAXVP] 13792
static constexpr int SGPA_OFF  = SVIDX_OFF + MAXVP * 2;     // float4[NGPP] 6912
static constexpr int SGPB_OFF  = SGPA_OFF + NGPP * 16;
static constexpr int SSPA_OFF  = SGPB_OFF + NGPP * 16;      // float4[NSP] 864
static constexpr int SSPB_OFF  = SSPA_OFF + NSP * 16;
static constexpr int SBONE_OFF = SSPB_OFF + NSP * 16;       // 1536
static constexpr int SSUPL_OFF = SBONE_OFF + 1536;          // u8 [(SCAP+1)*NTHR] 8704
static constexpr int SGRPL_OFF = SSUPL_OFF + (SCAP + 1) * NTHR;
static constexpr int SMEM_TOT  = SGRPL_OFF + (GCAP + 1) * NTHR * 2;   // 216480

__global__ void __launch_bounds__(NTHR, 1) nn_kernel(
    const float* __restrict__ xyz,
    const float* __restrict__ rot,
    const float* __restrict__ W,
    const float* __restrict__ bones,
    float* __restrict__ out,
    int n, int nv)
{
    extern __shared__ char smem[];
    ulonglong2* sVP  = reinterpret_cast<ulonglong2*>(smem + SVP_OFF);
    unsigned int* sVidx = reinterpret_cast<unsigned int*>(smem + SVIDX_OFF);
    ulonglong2* sGPA = reinterpret_cast<ulonglong2*>(smem + SGPA_OFF);
    ulonglong2* sGPB = reinterpret_cast<ulonglong2*>(smem + SGPB_OFF);
    ulonglong2* sSPA = reinterpret_cast<ulonglong2*>(smem + SSPA_OFF);
    ulonglong2* sSPB = reinterpret_cast<ulonglong2*>(smem + SSPB_OFF);
    float*          sB   = reinterpret_cast<float*>(smem + SBONE_OFF);
    unsigned char*  supL = reinterpret_cast<unsigned char*>(smem + SSUPL_OFF);
    unsigned short* grpL = reinterpret_cast<unsigned short*>(smem + SGRPL_OFF);

    const int tid = threadIdx.x;
    {
        float4* d = reinterpret_cast<float4*>(smem + SVP_OFF);
        for (int j = tid; j < MAXVP; j += NTHR) d[j] = g_vp[j];
        unsigned int* vi = reinterpret_cast<unsigned int*>(smem + SVIDX_OFF);
        const unsigned int* gvi = reinterpret_cast<const unsigned int*>(g_vidx16);
        for (int j = tid; j < MAXVP / 2; j += NTHR) vi[j] = gvi[j];
        float4* ga = reinterpret_cast<float4*>(smem + SGPA_OFF);
        float4* gb = reinterpret_cast<float4*>(smem + SGPB_OFF);
        for (int j = tid; j < NGPP; j += NTHR) { ga[j] = g_gpA[j]; gb[j] = g_gpB[j]; }
        float4* sa = reinterpret_cast<float4*>(smem + SSPA_OFF);
        float4* sbp = reinterpret_cast<float4*>(smem + SSPB_OFF);
        if (tid < NSP) { sa[tid] = g_spA[tid]; sbp[tid] = g_spB[tid]; }
        for (int j = tid; j < 24 * 16; j += NTHR) sB[j] = bones[j];
    }
    __syncthreads();

    const int i = blockIdx.x * NTHR + tid;
    const bool valid = (i < n);
    const int pid = g_order[valid ? i : (n - 1)];

    const float px = xyz[3 * pid + 0];
    const float py = xyz[3 * pid + 1];
    const float pz = xyz[3 * pid + 2];
    const float sx = __fadd_rn(__fadd_rn(__fmul_rn(px, px), __fmul_rn(py, py)),
                               __fmul_rn(pz, pz));

    const ull Px2 = f2_pack(px, px), Py2 = f2_pack(py, py), Pz2 = f2_pack(pz, pz);
    const ull NPx2 = f2_pack(-px, -px), NPy2 = f2_pack(-py, -py), NPz2 = f2_pack(-pz, -pz);
    const ull Sx2 = f2_pack(sx, sx), M2 = f2_pack(-2.0f, -2.0f);

    float bl = CUDART_INF_F;
    int   bi = 0x7FFFFFFF;

    auto evalg = [&](int g) {
        #pragma unroll
        for (int q = 0; q < 4; ++q) {
            int p = g * 4 + q;
            ulonglong2 ab = sVP[2 * p], cd = sVP[2 * p + 1];
            ull dot = f2_mul(Px2, ab.x);
            dot = f2_fma(Py2, ab.y, dot);
            dot = f2_fma(Pz2, cd.x, dot);
            float2 d = f2_unpack(f2_add(f2_fma(M2, dot, Sx2), cd.y));
            unsigned int ip = sVidx[p];
            int i0 = (int)(ip & 0xFFFFu), i1 = (int)(ip >> 16);
            bool b0 = (d.x < bl) || (d.x == bl && i0 < bi);
            bl = b0 ? d.x : bl;  bi = b0 ? i0 : bi;
            bool b1 = (d.y < bl) || (d.y == bl && i1 < bi);
            bl = b1 ? d.y : bl;  bi = b1 ? i1 : bi;
        }
    };

    // ── seed: groups around this point's Morton cell (exact eval)
    {
        int cid = morton_cell(px, py, pz);
        int vpos = g_vstart[cid];
        int gs = min(max(vpos >> 3, 0), NGRP - 1);
        evalg(max(gs - 1, 0));
        evalg(gs);
        evalg(min(gs + 1, NGRP - 1));
    }

    const float rs2 = (bl + 1e-3f) * 1.001f;
    const float rs  = sqrtf(rs2);
    const ull Rs2p  = f2_pack(rs2, rs2);
    const ull TwoRs = f2_pack(2.0f * rs, 2.0f * rs);

    // ── B1: super-pairs; dummy-slot compaction (lane-interleaved)
    int sc = 0;
    for (int sp = 0; sp < NSP; ++sp) {
        ulonglong2 A = sSPA[sp], B = sSPB[sp];
        ull dx = f2_add(A.x, NPx2);
        ull dy = f2_add(A.y, NPy2);
        ull dz = f2_add(B.x, NPz2);
        ull d2 = f2_mul(dx, dx);
        d2 = f2_fma(dy, dy, d2);
        d2 = f2_fma(dz, dz, d2);
        ull thr = f2_fma(B.y, B.y, Rs2p);
        thr = f2_fma(TwoRs, B.y, thr);
        float2 dd = f2_unpack(d2), tt = f2_unpack(thr);
        bool p0 = dd.x <= tt.x, p1 = dd.y <= tt.y;
        supL[(p0 ? min(sc, SCAP - 1) : SCAP) * NTHR + tid] = (unsigned char)(2 * sp);     sc += p0;
        supL[(p1 ? min(sc, SCAP - 1) : SCAP) * NTHR + tid] = (unsigned char)(2 * sp + 1); sc += p1;
    }
    const bool sofl = (sc > SCAP);

    // ── B2: groups of passing supers
    int gc = 0;
    const int nIt = sofl ? NSUPP : sc;
    for (int t = 0; t < nIt; ++t) {
        int sid = sofl ? t : (int)supL[t * NTHR + tid];
        #pragma unroll
        for (int q = 0; q < 4; ++q) {
            int gp = sid * 4 + q;          // < NGPP (padded, safe)
            ulonglong2 A = sGPA[gp], B = sGPB[gp];
            ull dx = f2_add(A.x, NPx2);
            ull dy = f2_add(A.y, NPy2);
            ull dz = f2_add(B.x, NPz2);
            ull d2 = f2_mul(dx, dx);
            d2 = f2_fma(dy, dy, d2);
            d2 = f2_fma(dz, dz, d2);
            ull thr = f2_fma(B.y, B.y, Rs2p);
            thr = f2_fma(TwoRs, B.y, thr);
            float2 dd = f2_unpack(d2), tt = f2_unpack(thr);
            bool p0 = dd.x <= tt.x, p1 = dd.y <= tt.y;
            grpL[(p0 ? min(gc, GCAP - 1) : GCAP) * NTHR + tid] = (unsigned short)(2 * gp);     gc += p0;
            grpL[(p1 ? min(gc, GCAP - 1) : GCAP) * NTHR + tid] = (unsigned short)(2 * gp + 1); gc += p1;
        }
    }
    const bool gofl = (gc > GCAP);

    // ── C: exact eval of candidate groups (all smem)
    const int nE = gofl ? NGRP : gc;
    for (int t = 0; t < nE; ++t) {
        int g = gofl ? t : (int)grpL[t * NTHR + tid];
        if (g >= NGRP) continue;
        evalg(g);
    }
    const int bidx = min(bi, nv - 1);

    if (!valid) return;

    // ── skinning epilogue ──
    float T[16];
    #pragma unroll
    for (int k = 0; k < 16; ++k) T[k] = 0.0f;
    const float* wrow = W + (size_t)bidx * 24;
    #pragma unroll
    for (int j = 0; j < 24; ++j) {
        float wj = __ldg(wrow + j);
        #pragma unroll
        for (int k = 0; k < 16; ++k) T[k] = fmaf(wj, sB[j * 16 + k], T[k]);
    }

    #pragma unroll
    for (int ii = 0; ii < 3; ++ii) {
        float v = T[4 * ii + 3];
        v = fmaf(T[4 * ii + 0], px, v);
        v = fmaf(T[4 * ii + 1], py, v);
        v = fmaf(T[4 * ii + 2], pz, v);
        out[3 * pid + ii] = v;
    }

    const float4 q = *reinterpret_cast<const float4*>(rot + 4 * pid);
    float qn = rsqrtf(q.x * q.x + q.y * q.y + q.z * q.z + q.w * q.w);
    float qr = q.x * qn, qx = q.y * qn, qy = q.z * qn, qz = q.w * qn;

    float R[3][3];
    R[0][0] = 1.0f - 2.0f * (qy * qy + qz * qz);
    R[0][1] = 2.0f * (qx * qy - qr * qz);
    R[0][2] = 2.0f * (qx * qz + qr * qy);
    R[1][0] = 2.0f * (qx * qy + qr * qz);
    R[1][1] = 1.0f - 2.0f * (qx * qx + qz * qz);
    R[1][2] = 2.0f * (qy * qz - qr * qx);
    R[2][0] = 2.0f * (qx * qz - qr * qy);
    R[2][1] = 2.0f * (qy * qz + qr * qx);
    R[2][2] = 1.0f - 2.0f * (qx * qx + qy * qy);

    float* out_R = out + (size_t)3 * n;
    #pragma unroll
    for (int ii = 0; ii < 3; ++ii) {
        #pragma unroll
        for (int k = 0; k < 3; ++k) {
            float v = T[4 * ii + 0] * R[0][k];
            v = fmaf(T[4 * ii + 1], R[1][k], v);
            v = fmaf(T[4 * ii + 2], R[2][k], v);
            out_R[9 * pid + 3 * ii + k] = v;
        }
    }

    float4* out_T = reinterpret_cast<float4*>(out + (size_t)12 * n) + (size_t)4 * pid;
    #pragma unroll
    for (int k = 0; k < 4; ++k)
        out_T[k] = make_float4(T[4 * k + 0], T[4 * k + 1], T[4 * k + 2], T[4 * k + 3]);
}

extern "C" void kernel_launch(void* const* d_in, const int* in_sizes, int n_in,
                              void* d_out, int out_size)
{
    const float* xyz   = (const float*)d_in[0];
    const float* rot   = (const float*)d_in[1];
    const float* verts = (const float*)d_in[2];
    const float* W     = (const float*)d_in[3];
    const float* bones = (const float*)d_in[4];
    float* out = (float*)d_out;

    const int n  = in_sizes[0] / 3;   // 100000
    const int nv = in_sizes[2] / 3;   // 6890
    const int mx = (n > nv) ? n : nv;

    cudaFuncSetAttribute(nn_kernel,
                         cudaFuncAttributeMaxDynamicSharedMemorySize, SMEM_TOT);

    zero_counts<<<NCELLS / 256, 256>>>(nv);
    count_kernel<<<(mx + 255) / 256, 256>>>(verts, xyz, nv, n);
    scan_offsets<<<2, 1024>>>();
    scatter_kernel<<<(mx + 255) / 256, 256>>>(verts, nv, n);
    bounds_kernel<<<1, 1024>>>(nv);
    nn_kernel<<<(n + NTHR - 1) / NTHR, NTHR, SMEM_TOT>>>(xyz, rot, W, bones, out, n, nv);
}

// round 16
// speedup vs baseline: 1.4086x; 1.4086x over previous
#include <cuda_runtime.h>
#include <math_constants.h>
#include <float.h>

// SMPL NN skinning — Morton-sorted verts AND points; ONE WARP = 32 coherent
// points sharing ONE candidate-group list (ballot-compacted, no caps).
// Flat prune over all 862 group spheres vs the warp bbox + warp-max radius.
// Eval loop is warp-uniform; vert table in smem -> broadcast LDS.
// Every visited vert uses the bit-exact reference d2; per-lane lex (d2,idx)
// min == jnp.argmin first-index (order-independent).
// Output: [0,3n) x_bar | [3n,12n) rotation_bar | [12n,28n) T_fwd

typedef unsigned long long ull;

__device__ __forceinline__ ull f2_mul(ull a, ull b) {
    ull r; asm("mul.rn.f32x2 %0,%1,%2;" : "=l"(r) : "l"(a), "l"(b)); return r;
}
__device__ __forceinline__ ull f2_fma(ull a, ull b, ull c) {
    ull r; asm("fma.rn.f32x2 %0,%1,%2,%3;" : "=l"(r) : "l"(a), "l"(b), "l"(c)); return r;
}
__device__ __forceinline__ ull f2_add(ull a, ull b) {
    ull r; asm("add.rn.f32x2 %0,%1,%2;" : "=l"(r) : "l"(a), "l"(b)); return r;
}
__device__ __forceinline__ ull f2_pack(float lo, float hi) {
    ull r; asm("mov.b64 %0,{%1,%2};" : "=l"(r) : "f"(lo), "f"(hi)); return r;
}
__device__ __forceinline__ float2 f2_unpack(ull v) {
    float lo, hi; asm("mov.b64 {%0,%1},%2;" : "=f"(lo), "=f"(hi) : "l"(v));
    return make_float2(lo, hi);
}

static constexpr int   NC     = 16;
static constexpr int   NCELLS = NC * NC * NC;     // 4096
static constexpr float ORG    = -4.0f;
static constexpr float INV_CS = 2.0f;
static constexpr int   MAXN   = 100000;
static constexpr int   MAXVP  = 6896;             // mult of 16
static constexpr int   NPAIRS = MAXVP / 2;
static constexpr int   NGRP   = MAXVP / 8;        // 862
static constexpr int   NTHR   = 512;              // 16 warps, 1 CTA/SM
static constexpr int   NWARP  = NTHR / 32;
static constexpr int   WCAP   = 864;              // full list, no overflow

// vert side
__device__ int    g_vcount[NCELLS];
__device__ int    g_vstart[NCELLS + 1];
__device__ int    g_vrank[MAXVP];
__device__ int    g_vcellid[MAXVP];
__device__ float4 g_vs[MAXVP];
__device__ int    g_vidx[MAXVP];
__device__ float4 g_vp[MAXVP];                    // pair-packed verts
__device__ unsigned short g_vidx16[MAXVP];
__device__ float4 g_gb[NGRP];                     // group spheres (cx,cy,cz,rad)
// point side
__device__ int    g_pcount[NCELLS];
__device__ int    g_pstart[NCELLS + 1];
__device__ int    g_prank[MAXN];
__device__ int    g_pcellid[MAXN];
__device__ int    g_order[MAXN];

__device__ __forceinline__ int cell_coord(float x) {
    int c = (int)floorf((x - ORG) * INV_CS);
    return min(NC - 1, max(0, c));
}
__device__ __forceinline__ int spread4(int v) {
    return (v & 1) | ((v & 2) << 2) | ((v & 4) << 4) | ((v & 8) << 6);
}
__device__ __forceinline__ int morton_cell(float x, float y, float z) {
    return spread4(cell_coord(x)) | (spread4(cell_coord(y)) << 1)
         | (spread4(cell_coord(z)) << 2);
}

// ───────────── build kernels (proven R14 pipeline) ─────────────
__global__ void zero_counts(int nv) {
    int i = blockIdx.x * blockDim.x + threadIdx.x;   // 4096
    if (i < NCELLS) { g_vcount[i] = 0; g_pcount[i] = 0; }
    for (int k = nv + i; k < MAXVP; k += NCELLS) {
        g_vs[k]   = make_float4(1e7f, 1e7f, 1e7f, CUDART_INF_F);
        g_vidx[k] = 0xFFFF;
    }
}

__global__ void count_kernel(const float* __restrict__ verts,
                             const float* __restrict__ xyz, int nv, int n) {
    int i = blockIdx.x * blockDim.x + threadIdx.x;
    if (i < nv) {
        int cid = morton_cell(verts[3 * i], verts[3 * i + 1], verts[3 * i + 2]);
        g_vcellid[i] = cid;
        g_vrank[i] = atomicAdd(&g_vcount[cid], 1);
    }
    if (i < n) {
        int cid = morton_cell(xyz[3 * i], xyz[3 * i + 1], xyz[3 * i + 2]);
        g_pcellid[i] = cid;
        g_prank[i] = atomicAdd(&g_pcount[cid], 1);
    }
}

__global__ void __launch_bounds__(1024) scan_offsets() {
    __shared__ int part[1024];
    const int t = threadIdx.x;
    int* cnt = blockIdx.x ? g_pcount : g_vcount;
    int* st  = blockIdx.x ? g_pstart : g_vstart;
    const int CHUNK = NCELLS / 1024;   // 4
    int base = t * CHUNK, s = 0;
    #pragma unroll
    for (int k = 0; k < CHUNK; ++k) s += cnt[base + k];
    part[t] = s;
    __syncthreads();
    for (int off = 1; off < 1024; off <<= 1) {
        int v = (t >= off) ? part[t - off] : 0;
        __syncthreads(); part[t] += v; __syncthreads();
    }
    int excl = part[t] - s;
    #pragma unroll
    for (int k = 0; k < CHUNK; ++k) { st[base + k] = excl; excl += cnt[base + k]; }
    if (t == 1023) st[NCELLS] = part[1023];
}

__global__ void scatter_kernel(const float* __restrict__ verts, int nv, int n) {
    int i = blockIdx.x * blockDim.x + threadIdx.x;
    if (i < nv) {
        float x = verts[3 * i], y = verts[3 * i + 1], z = verts[3 * i + 2];
        float sv = __fadd_rn(__fadd_rn(__fmul_rn(x, x), __fmul_rn(y, y)),
                             __fmul_rn(z, z));
        int pos = g_vstart[g_vcellid[i]] + g_vrank[i];
        g_vs[pos]   = make_float4(x, y, z, sv);
        g_vidx[pos] = i;
    }
    if (i < n) g_order[g_pstart[g_pcellid[i]] + g_prank[i]] = i;
}

__global__ void __launch_bounds__(1024) bounds_kernel(int nv) {
    const int tid = threadIdx.x;
    // group spheres (empty groups pushed far away)
    for (int g = tid; g < NGRP; g += 1024) {
        float mnx = FLT_MAX, mny = FLT_MAX, mnz = FLT_MAX;
        float mxx = -FLT_MAX, mxy = -FLT_MAX, mxz = -FLT_MAX;
        bool any = false;
        #pragma unroll
        for (int k = 0; k < 8; ++k) {
            float4 v = g_vs[g * 8 + k];
            if (isinf(v.w)) continue;
            any = true;
            mnx = fminf(mnx, v.x); mxx = fmaxf(mxx, v.x);
            mny = fminf(mny, v.y); mxy = fmaxf(mxy, v.y);
            mnz = fminf(mnz, v.z); mxz = fmaxf(mxz, v.z);
        }
        if (!any) {
            g_gb[g] = make_float4(1e7f, 1e7f, 1e7f, 0.f);
        } else {
            float cx = 0.5f * (mnx + mxx), cy = 0.5f * (mny + mxy), cz = 0.5f * (mnz + mxz);
            float m2 = 0.f;
            #pragma unroll
            for (int k = 0; k < 8; ++k) {
                float4 v = g_vs[g * 8 + k];
                if (isinf(v.w)) continue;
                float dx = v.x - cx, dy = v.y - cy, dz = v.z - cz;
                m2 = fmaxf(m2, dx * dx + dy * dy + dz * dz);
            }
            g_gb[g] = make_float4(cx, cy, cz, sqrtf(m2) * 1.0002f + 1e-5f);
        }
    }
    // pair-pack verts + idx16
    for (int p = tid; p < NPAIRS; p += 1024) {
        float4 v0 = g_vs[2 * p], v1 = g_vs[2 * p + 1];
        g_vp[2 * p]     = make_float4(v0.x, v1.x, v0.y, v1.y);
        g_vp[2 * p + 1] = make_float4(v0.z, v1.z, v0.w, v1.w);
        g_vidx16[2 * p]     = (unsigned short)g_vidx[2 * p];
        g_vidx16[2 * p + 1] = (unsigned short)g_vidx[2 * p + 1];
    }
}

// ─────────── NN + skinning: warp-shared candidate list ───────────
static constexpr int SVP_OFF   = 0;                        // float4[MAXVP] 110336
static constexpr int SVIDX_OFF = SVP_OFF + MAXVP * 16;     // u16[MAXVP] 13792
static constexpr int SGB_OFF   = SVIDX_OFF + MAXVP * 2;    // float4[NGRP] 13792
static constexpr int SBONE_OFF = SGB_OFF + NGRP * 16;      // 1536
static constexpr int SWL_OFF   = SBONE_OFF + 1536;         // u16[NWARP][WCAP] 27648
static constexpr int SMEM_TOT  = SWL_OFF + NWARP * WCAP * 2;   // 167104

__global__ void __launch_bounds__(NTHR, 1) nn_kernel(
    const float* __restrict__ xyz,
    const float* __restrict__ rot,
    const float* __restrict__ W,
    const float* __restrict__ bones,
    float* __restrict__ out,
    int n, int nv)
{
    extern __shared__ char smem[];
    ulonglong2*   sVP   = reinterpret_cast<ulonglong2*>(smem + SVP_OFF);
    unsigned int* sVidx = reinterpret_cast<unsigned int*>(smem + SVIDX_OFF);
    float4*       sGB   = reinterpret_cast<float4*>(smem + SGB_OFF);
    float*        sB    = reinterpret_cast<float*>(smem + SBONE_OFF);

    const int tid  = threadIdx.x;
    const int lane = tid & 31;
    const int wid  = tid >> 5;
    unsigned short* wl = reinterpret_cast<unsigned short*>(smem + SWL_OFF) + wid * WCAP;

    {   // cooperative smem fill
        float4* d = reinterpret_cast<float4*>(smem + SVP_OFF);
        for (int j = tid; j < MAXVP; j += NTHR) d[j] = g_vp[j];
        unsigned int* vi = reinterpret_cast<unsigned int*>(smem + SVIDX_OFF);
        const unsigned int* gvi = reinterpret_cast<const unsigned int*>(g_vidx16);
        for (int j = tid; j < MAXVP / 2; j += NTHR) vi[j] = gvi[j];
        for (int j = tid; j < NGRP; j += NTHR) sGB[j] = g_gb[j];
        for (int j = tid; j < 24 * 16; j += NTHR) sB[j] = bones[j];
    }
    __syncthreads();

    const int i = blockIdx.x * NTHR + tid;
    const bool valid = (i < n);
    const int pid = g_order[valid ? i : (n - 1)];

    const float px = xyz[3 * pid + 0];
    const float py = xyz[3 * pid + 1];
    const float pz = xyz[3 * pid + 2];
    const float sx = __fadd_rn(__fadd_rn(__fmul_rn(px, px), __fmul_rn(py, py)),
                               __fmul_rn(pz, pz));

    const ull Px2 = f2_pack(px, px), Py2 = f2_pack(py, py), Pz2 = f2_pack(pz, pz);
    const ull Sx2 = f2_pack(sx, sx), M2 = f2_pack(-2.0f, -2.0f);

    float bl = CUDART_INF_F;
    int   bi = 0x7FFFFFFF;

    auto evalg = [&](int g) {
        #pragma unroll
        for (int q = 0; q < 4; ++q) {
            int p = g * 4 + q;
            ulonglong2 ab = sVP[2 * p], cd = sVP[2 * p + 1];
            ull dot = f2_mul(Px2, ab.x);
            dot = f2_fma(Py2, ab.y, dot);
            dot = f2_fma(Pz2, cd.x, dot);
            float2 d = f2_unpack(f2_add(f2_fma(M2, dot, Sx2), cd.y));
            unsigned int ip = sVidx[p];
            int i0 = (int)(ip & 0xFFFFu), i1 = (int)(ip >> 16);
            bool b0 = (d.x < bl) || (d.x == bl && i0 < bi);
            bl = b0 ? d.x : bl;  bi = b0 ? i0 : bi;
            bool b1 = (d.y < bl) || (d.y == bl && i1 < bi);
            bl = b1 ? d.y : bl;  bi = b1 ? i1 : bi;
        }
    };

    // ── per-lane seed: 3 groups at own Morton cell (exact eval)
    {
        int cid = morton_cell(px, py, pz);
        int gs = min(max(g_vstart[cid] >> 3, 0), NGRP - 1);
        evalg(max(gs - 1, 0));
        evalg(gs);
        evalg(min(gs + 1, NGRP - 1));
    }

    // ── warp bound: bbox of points + warp-max search radius
    float lox = px, hix = px, loy = py, hiy = py, loz = pz, hiz = pz;
    float s = sqrtf(bl + 1e-3f) * 1.0005f;
    #pragma unroll
    for (int o = 16; o; o >>= 1) {
        lox = fminf(lox, __shfl_xor_sync(0xFFFFFFFFu, lox, o));
        hix = fmaxf(hix, __shfl_xor_sync(0xFFFFFFFFu, hix, o));
        loy = fminf(loy, __shfl_xor_sync(0xFFFFFFFFu, loy, o));
        hiy = fmaxf(hiy, __shfl_xor_sync(0xFFFFFFFFu, hiy, o));
        loz = fminf(loz, __shfl_xor_sync(0xFFFFFFFFu, loz, o));
        hiz = fmaxf(hiz, __shfl_xor_sync(0xFFFFFFFFu, hiz, o));
        s   = fmaxf(s,   __shfl_xor_sync(0xFFFFFFFFu, s, o));
    }
    const float smax = s;

    // ── flat prune: 862 groups, 27 tests/lane, ballot-compact ONE warp list
    int gc = 0;
    #pragma unroll 1
    for (int base = 0; base < NGRP; base += 32) {
        int g = base + lane;
        bool pass = false;
        if (g < NGRP) {
            float4 b = sGB[g];
            float dx = fmaxf(0.f, fmaxf(lox - b.x, b.x - hix));
            float dy = fmaxf(0.f, fmaxf(loy - b.y, b.y - hiy));
            float dz = fmaxf(0.f, fmaxf(loz - b.z, b.z - hiz));
            float thr = (smax + b.w) * 1.0005f + 1e-4f;
            pass = (dx * dx + dy * dy + dz * dz) <= thr * thr;
        }
        unsigned m = __ballot_sync(0xFFFFFFFFu, pass);
        if (pass) wl[gc + __popc(m & ((1u << lane) - 1))] = (unsigned short)g;
        gc += __popc(m);
    }

    // ── uniform eval of the shared list (broadcast LDS, branch-free)
    for (int t = 0; t < gc; ++t) evalg((int)wl[t]);

    const int bidx = min(bi, nv - 1);
    if (!valid) return;

    // ── skinning epilogue ──
    float T[16];
    #pragma unroll
    for (int k = 0; k < 16; ++k) T[k] = 0.0f;
    const float* wrow = W + (size_t)bidx * 24;
    #pragma unroll
    for (int j = 0; j < 24; ++j) {
        float wj = __ldg(wrow + j);
        #pragma unroll
        for (int k = 0; k < 16; ++k) T[k] = fmaf(wj, sB[j * 16 + k], T[k]);
    }

    #pragma unroll
    for (int ii = 0; ii < 3; ++ii) {
        float v = T[4 * ii + 3];
        v = fmaf(T[4 * ii + 0], px, v);
        v = fmaf(T[4 * ii + 1], py, v);
        v = fmaf(T[4 * ii + 2], pz, v);
        out[3 * pid + ii] = v;
    }

    const float4 q = *reinterpret_cast<const float4*>(rot + 4 * pid);
    float qn = rsqrtf(q.x * q.x + q.y * q.y + q.z * q.z + q.w * q.w);
    float qr = q.x * qn, qx = q.y * qn, qy = q.z * qn, qz = q.w * qn;

    float R[3][3];
    R[0][0] = 1.0f - 2.0f * (qy * qy + qz * qz);
    R[0][1] = 2.0f * (qx * qy - qr * qz);
    R[0][2] = 2.0f * (qx * qz + qr * qy);
    R[1][0] = 2.0f * (qx * qy + qr * qz);
    R[1][1] = 1.0f - 2.0f * (qx * qx + qz * qz);
    R[1][2] = 2.0f * (qy * qz - qr * qx);
    R[2][0] = 2.0f * (qx * qz - qr * qy);
    R[2][1] = 2.0f * (qy * qz + qr * qx);
    R[2][2] = 1.0f - 2.0f * (qx * qx + qy * qy);

    float* out_R = out + (size_t)3 * n;
    #pragma unroll
    for (int ii = 0; ii < 3; ++ii) {
        #pragma unroll
        for (int k = 0; k < 3; ++k) {
            float v = T[4 * ii + 0] * R[0][k];
            v = fmaf(T[4 * ii + 1], R[1][k], v);
            v = fmaf(T[4 * ii + 2], R[2][k], v);
            out_R[9 * pid + 3 * ii + k] = v;
        }
    }

    float4* out_T = reinterpret_cast<float4*>(out + (size_t)12 * n) + (size_t)4 * pid;
    #pragma unroll
    for (int k = 0; k < 4; ++k)
        out_T[k] = make_float4(T[4 * k + 0], T[4 * k + 1], T[4 * k + 2], T[4 * k + 3]);
}

extern "C" void kernel_launch(void* const* d_in, const int* in_sizes, int n_in,
                              void* d_out, int out_size)
{
    const float* xyz   = (const float*)d_in[0];
    const float* rot   = (const float*)d_in[1];
    const float* verts = (const float*)d_in[2];
    const float* W     = (const float*)d_in[3];
    const float* bones = (const float*)d_in[4];
    float* out = (float*)d_out;

    const int n  = in_sizes[0] / 3;   // 100000
    const int nv = in_sizes[2] / 3;   // 6890
    const int mx = (n > nv) ? n : nv;

    cudaFuncSetAttribute(nn_kernel,
                         cudaFuncAttributeMaxDynamicSharedMemorySize, SMEM_TOT);

    zero_counts<<<NCELLS / 256, 256>>>(nv);
    count_kernel<<<(mx + 255) / 256, 256>>>(verts, xyz, nv, n);
    scan_offsets<<<2, 1024>>>();
    scatter_kernel<<<(mx + 255) / 256, 256>>>(verts, nv, n);
    bounds_kernel<<<1, 1024>>>(nv);
    nn_kernel<<<(n + NTHR - 1) / NTHR, NTHR, SMEM_TOT>>>(xyz, rot, W, bones, out, n, nv);
}

// round 17
// speedup vs baseline: 2.9053x; 2.0626x over previous
#include <cuda_runtime.h>
#include <math_constants.h>
#include <float.h>

// SMPL NN skinning — Morton-sorted verts AND points; warp-uniform two-level
// traversal with PER-LANE tight radii and ballot-UNION candidate lists.
// Eval loop warp-uniform (broadcast LDS from smem vert table); per-lane
// exact lex (d2, idx) argmin == jnp.argmin first-index.
// Output: [0,3n) x_bar | [3n,12n) rotation_bar | [12n,28n) T_fwd

typedef unsigned long long ull;

__device__ __forceinline__ ull f2_mul(ull a, ull b) {
    ull r; asm("mul.rn.f32x2 %0,%1,%2;" : "=l"(r) : "l"(a), "l"(b)); return r;
}
__device__ __forceinline__ ull f2_fma(ull a, ull b, ull c) {
    ull r; asm("fma.rn.f32x2 %0,%1,%2,%3;" : "=l"(r) : "l"(a), "l"(b), "l"(c)); return r;
}
__device__ __forceinline__ ull f2_add(ull a, ull b) {
    ull r; asm("add.rn.f32x2 %0,%1,%2;" : "=l"(r) : "l"(a), "l"(b)); return r;
}
__device__ __forceinline__ ull f2_pack(float lo, float hi) {
    ull r; asm("mov.b64 %0,{%1,%2};" : "=l"(r) : "f"(lo), "f"(hi)); return r;
}
__device__ __forceinline__ float2 f2_unpack(ull v) {
    float lo, hi; asm("mov.b64 {%0,%1},%2;" : "=f"(lo), "=f"(hi) : "l"(v));
    return make_float2(lo, hi);
}

static constexpr int   NC     = 16;
static constexpr int   NCELLS = NC * NC * NC;     // 4096
static constexpr float ORG    = -4.0f;
static constexpr float INV_CS = 2.0f;
static constexpr int   MAXN   = 100000;
static constexpr int   MAXVP  = 6896;             // mult of 16
static constexpr int   NPAIRS = MAXVP / 2;
static constexpr int   NGRP   = MAXVP / 8;        // 862
static constexpr int   NGRPP  = 864;              // padded groups (108*8)
static constexpr int   NSUPP  = 108;
static constexpr int   NTHR   = 512;              // 16 warps, 1 CTA/SM
static constexpr int   NWARP  = NTHR / 32;

// vert side
__device__ int    g_vcount[NCELLS];
__device__ int    g_vstart[NCELLS + 1];
__device__ int    g_vrank[MAXVP];
__device__ int    g_vcellid[MAXVP];
__device__ float4 g_vs[MAXVP];
__device__ int    g_vidx[MAXVP];
__device__ float4 g_vp[MAXVP];                    // pair-packed verts
__device__ unsigned short g_vidx16[MAXVP];
__device__ float4 g_gb[NGRPP];                    // group spheres (padded far)
__device__ float4 g_sb[NSUPP];                    // super spheres
// point side
__device__ int    g_pcount[NCELLS];
__device__ int    g_pstart[NCELLS + 1];
__device__ int    g_prank[MAXN];
__device__ int    g_pcellid[MAXN];
__device__ int    g_order[MAXN];

__device__ __forceinline__ int cell_coord(float x) {
    int c = (int)floorf((x - ORG) * INV_CS);
    return min(NC - 1, max(0, c));
}
__device__ __forceinline__ int spread4(int v) {
    return (v & 1) | ((v & 2) << 2) | ((v & 4) << 4) | ((v & 8) << 6);
}
__device__ __forceinline__ int morton_cell(float x, float y, float z) {
    return spread4(cell_coord(x)) | (spread4(cell_coord(y)) << 1)
         | (spread4(cell_coord(z)) << 2);
}

// ───────────── build kernels (proven pipeline) ─────────────
__global__ void zero_counts(int nv) {
    int i = blockIdx.x * blockDim.x + threadIdx.x;   // 4096
    if (i < NCELLS) { g_vcount[i] = 0; g_pcount[i] = 0; }
    for (int k = nv + i; k < MAXVP; k += NCELLS) {
        g_vs[k]   = make_float4(1e7f, 1e7f, 1e7f, CUDART_INF_F);
        g_vidx[k] = 0xFFFF;
    }
}

__global__ void count_kernel(const float* __restrict__ verts,
                             const float* __restrict__ xyz, int nv, int n) {
    int i = blockIdx.x * blockDim.x + threadIdx.x;
    if (i < nv) {
        int cid = morton_cell(verts[3 * i], verts[3 * i + 1], verts[3 * i + 2]);
        g_vcellid[i] = cid;
        g_vrank[i] = atomicAdd(&g_vcount[cid], 1);
    }
    if (i < n) {
        int cid = morton_cell(xyz[3 * i], xyz[3 * i + 1], xyz[3 * i + 2]);
        g_pcellid[i] = cid;
        g_prank[i] = atomicAdd(&g_pcount[cid], 1);
    }
}

__global__ void __launch_bounds__(1024) scan_offsets() {
    __shared__ int part[1024];
    const int t = threadIdx.x;
    int* cnt = blockIdx.x ? g_pcount : g_vcount;
    int* st  = blockIdx.x ? g_pstart : g_vstart;
    const int CHUNK = NCELLS / 1024;   // 4
    int base = t * CHUNK, s = 0;
    #pragma unroll
    for (int k = 0; k < CHUNK; ++k) s += cnt[base + k];
    part[t] = s;
    __syncthreads();
    for (int off = 1; off < 1024; off <<= 1) {
        int v = (t >= off) ? part[t - off] : 0;
        __syncthreads(); part[t] += v; __syncthreads();
    }
    int excl = part[t] - s;
    #pragma unroll
    for (int k = 0; k < CHUNK; ++k) { st[base + k] = excl; excl += cnt[base + k]; }
    if (t == 1023) st[NCELLS] = part[1023];
}

__global__ void scatter_kernel(const float* __restrict__ verts, int nv, int n) {
    int i = blockIdx.x * blockDim.x + threadIdx.x;
    if (i < nv) {
        float x = verts[3 * i], y = verts[3 * i + 1], z = verts[3 * i + 2];
        float sv = __fadd_rn(__fadd_rn(__fmul_rn(x, x), __fmul_rn(y, y)),
                             __fmul_rn(z, z));
        int pos = g_vstart[g_vcellid[i]] + g_vrank[i];
        g_vs[pos]   = make_float4(x, y, z, sv);
        g_vidx[pos] = i;
    }
    if (i < n) g_order[g_pstart[g_pcellid[i]] + g_prank[i]] = i;
}

__global__ void __launch_bounds__(1024) bounds_kernel(int nv) {
    __shared__ float4 sgb[NGRPP];
    const int tid = threadIdx.x;

    for (int g = tid; g < NGRPP; g += 1024) {
        float4 b = make_float4(1e7f, 1e7f, 1e7f, 0.f);
        if (g < NGRP) {
            float mnx = FLT_MAX, mny = FLT_MAX, mnz = FLT_MAX;
            float mxx = -FLT_MAX, mxy = -FLT_MAX, mxz = -FLT_MAX;
            bool any = false;
            #pragma unroll
            for (int k = 0; k < 8; ++k) {
                float4 v = g_vs[g * 8 + k];
                if (isinf(v.w)) continue;
                any = true;
                mnx = fminf(mnx, v.x); mxx = fmaxf(mxx, v.x);
                mny = fminf(mny, v.y); mxy = fmaxf(mxy, v.y);
                mnz = fminf(mnz, v.z); mxz = fmaxf(mxz, v.z);
            }
            if (any) {
                float cx = 0.5f * (mnx + mxx), cy = 0.5f * (mny + mxy), cz = 0.5f * (mnz + mxz);
                float m2 = 0.f;
                #pragma unroll
                for (int k = 0; k < 8; ++k) {
                    float4 v = g_vs[g * 8 + k];
                    if (isinf(v.w)) continue;
                    float dx = v.x - cx, dy = v.y - cy, dz = v.z - cz;
                    m2 = fmaxf(m2, dx * dx + dy * dy + dz * dz);
                }
                b = make_float4(cx, cy, cz, sqrtf(m2) * 1.0002f + 1e-5f);
            }
        }
        sgb[g] = b;
        g_gb[g] = b;
    }
    __syncthreads();

    if (tid < NSUPP) {
        float mnx = FLT_MAX, mny = FLT_MAX, mnz = FLT_MAX;
        float mxx = -FLT_MAX, mxy = -FLT_MAX, mxz = -FLT_MAX;
        bool any = false;
        #pragma unroll
        for (int k = 0; k < 8; ++k) {
            float4 b = sgb[tid * 8 + k];
            if (b.x > 9e6f) continue;
            any = true;
            mnx = fminf(mnx, b.x - b.w); mxx = fmaxf(mxx, b.x + b.w);
            mny = fminf(mny, b.y - b.w); mxy = fmaxf(mxy, b.y + b.w);
            mnz = fminf(mnz, b.z - b.w); mxz = fmaxf(mxz, b.z + b.w);
        }
        if (!any) {
            g_sb[tid] = make_float4(1e7f, 1e7f, 1e7f, 0.f);
        } else {
            float cx = 0.5f * (mnx + mxx), cy = 0.5f * (mny + mxy), cz = 0.5f * (mnz + mxz);
            float mr = 0.f;
            #pragma unroll
            for (int k = 0; k < 8; ++k) {
                float4 b = sgb[tid * 8 + k];
                if (b.x > 9e6f) continue;
                float dx = b.x - cx, dy = b.y - cy, dz = b.z - cz;
                mr = fmaxf(mr, sqrtf(dx * dx + dy * dy + dz * dz) + b.w);
            }
            g_sb[tid] = make_float4(cx, cy, cz, mr * 1.0002f + 1e-5f);
        }
    }

    for (int p = tid; p < NPAIRS; p += 1024) {
        float4 v0 = g_vs[2 * p], v1 = g_vs[2 * p + 1];
        g_vp[2 * p]     = make_float4(v0.x, v1.x, v0.y, v1.y);
        g_vp[2 * p + 1] = make_float4(v0.z, v1.z, v0.w, v1.w);
        g_vidx16[2 * p]     = (unsigned short)g_vidx[2 * p];
        g_vidx16[2 * p + 1] = (unsigned short)g_vidx[2 * p + 1];
    }
}

// ─────────── NN + skinning: per-lane tests, ballot-union lists ───────────
static constexpr int SVP_OFF   = 0;                        // float4[MAXVP] 110336
static constexpr int SVIDX_OFF = SVP_OFF + MAXVP * 16;     // u16[MAXVP] 13792
static constexpr int SGB_OFF   = SVIDX_OFF + MAXVP * 2;    // float4[NGRPP] 13824
static constexpr int SSB_OFF   = SGB_OFF + NGRPP * 16;     // float4[NSUPP] 1728
static constexpr int SBONE_OFF = SSB_OFF + NSUPP * 16;     // 1536
static constexpr int SWSUP_OFF = SBONE_OFF + 1536;         // u8 [NWARP][112]
static constexpr int SWL_OFF   = SWSUP_OFF + NWARP * 112;  // u16[NWARP][NGRPP]
static constexpr int SMEM_TOT  = SWL_OFF + NWARP * NGRPP * 2;   // ~170.6 KB

__global__ void __launch_bounds__(NTHR, 1) nn_kernel(
    const float* __restrict__ xyz,
    const float* __restrict__ rot,
    const float* __restrict__ W,
    const float* __restrict__ bones,
    float* __restrict__ out,
    int n, int nv)
{
    extern __shared__ char smem[];
    ulonglong2*   sVP   = reinterpret_cast<ulonglong2*>(smem + SVP_OFF);
    unsigned int* sVidx = reinterpret_cast<unsigned int*>(smem + SVIDX_OFF);
    float4*       sGB   = reinterpret_cast<float4*>(smem + SGB_OFF);
    float4*       sSB   = reinterpret_cast<float4*>(smem + SSB_OFF);
    float*        sB    = reinterpret_cast<float*>(smem + SBONE_OFF);

    const int tid  = threadIdx.x;
    const int lane = tid & 31;
    const int wid  = tid >> 5;
    unsigned char*  ws = reinterpret_cast<unsigned char*>(smem + SWSUP_OFF) + wid * 112;
    unsigned short* wl = reinterpret_cast<unsigned short*>(smem + SWL_OFF) + wid * NGRPP;

    {   // cooperative smem fill
        float4* d = reinterpret_cast<float4*>(smem + SVP_OFF);
        for (int j = tid; j < MAXVP; j += NTHR) d[j] = g_vp[j];
        unsigned int* vi = reinterpret_cast<unsigned int*>(smem + SVIDX_OFF);
        const unsigned int* gvi = reinterpret_cast<const unsigned int*>(g_vidx16);
        for (int j = tid; j < MAXVP / 2; j += NTHR) vi[j] = gvi[j];
        for (int j = tid; j < NGRPP; j += NTHR) sGB[j] = g_gb[j];
        if (tid < NSUPP) sSB[tid] = g_sb[tid];
        for (int j = tid; j < 24 * 16; j += NTHR) sB[j] = bones[j];
    }
    __syncthreads();

    const int i = blockIdx.x * NTHR + tid;
    const bool valid = (i < n);
    const int pid = g_order[valid ? i : (n - 1)];

    const float px = xyz[3 * pid + 0];
    const float py = xyz[3 * pid + 1];
    const float pz = xyz[3 * pid + 2];
    const float sx = __fadd_rn(__fadd_rn(__fmul_rn(px, px), __fmul_rn(py, py)),
                               __fmul_rn(pz, pz));

    const ull Px2 = f2_pack(px, px), Py2 = f2_pack(py, py), Pz2 = f2_pack(pz, pz);
    const ull Sx2 = f2_pack(sx, sx), M2 = f2_pack(-2.0f, -2.0f);

    float bl = CUDART_INF_F;
    int   bi = 0x7FFFFFFF;

    auto evalg = [&](int g) {
        #pragma unroll
        for (int q = 0; q < 4; ++q) {
            int p = g * 4 + q;
            ulonglong2 ab = sVP[2 * p], cd = sVP[2 * p + 1];
            ull dot = f2_mul(Px2, ab.x);
            dot = f2_fma(Py2, ab.y, dot);
            dot = f2_fma(Pz2, cd.x, dot);
            float2 d = f2_unpack(f2_add(f2_fma(M2, dot, Sx2), cd.y));
            unsigned int ip = sVidx[p];
            int i0 = (int)(ip & 0xFFFFu), i1 = (int)(ip >> 16);
            bool b0 = (d.x < bl) || (d.x == bl && i0 < bi);
            bl = b0 ? d.x : bl;  bi = b0 ? i0 : bi;
            bool b1 = (d.y < bl) || (d.y == bl && i1 < bi);
            bl = b1 ? d.y : bl;  bi = b1 ? i1 : bi;
        }
    };

    // ── per-lane seed: 3 groups at own Morton cell (exact eval)
    {
        int cid = morton_cell(px, py, pz);
        int gs = min(max(g_vstart[cid] >> 3, 0), NGRP - 1);
        evalg(max(gs - 1, 0));
        evalg(gs);
        evalg(min(gs + 1, NGRP - 1));
    }
    const float rs = sqrtf(bl + 1e-3f) * 1.0005f;   // per-lane tight radius

    // ── super pass: per-lane test, ballot-union (warp-uniform loop)
    int sc = 0;
    for (int s = 0; s < NSUPP; ++s) {
        float4 b = sSB[s];
        float dx = px - b.x, dy = py - b.y, dz = pz - b.z;
        float d2c = dx * dx + dy * dy + dz * dz;
        float thr = rs + b.w;
        bool pass = d2c <= thr * thr;
        unsigned m = __ballot_sync(0xFFFFFFFFu, pass);
        if (m) { if (lane == 0) ws[sc] = (unsigned char)s; ++sc; }
    }
    __syncwarp();

    // ── group pass: per-lane test of passing supers' groups, ballot-union
    int gc = 0;
    for (int t = 0; t < sc; ++t) {
        int sid = ws[t];
        #pragma unroll
        for (int k = 0; k < 8; ++k) {
            int g = sid * 8 + k;                    // < NGRPP, pads are far
            float4 b = sGB[g];
            float dx = px - b.x, dy = py - b.y, dz = pz - b.z;
            float d2c = dx * dx + dy * dy + dz * dz;
            float thr = rs + b.w;
            bool pass = d2c <= thr * thr;
            unsigned m = __ballot_sync(0xFFFFFFFFu, pass);
            if (m) { if (lane == 0) wl[gc] = (unsigned short)g; ++gc; }
        }
    }
    __syncwarp();

    // ── eval: warp-uniform over the union list (broadcast LDS)
    for (int t = 0; t < gc; ++t) evalg((int)wl[t]);

    const int bidx = min(bi, nv - 1);
    if (!valid) return;

    // ── skinning epilogue ──
    float T[16];
    #pragma unroll
    for (int k = 0; k < 16; ++k) T[k] = 0.0f;
    const float* wrow = W + (size_t)bidx * 24;
    #pragma unroll
    for (int j = 0; j < 24; ++j) {
        float wj = __ldg(wrow + j);
        #pragma unroll
        for (int k = 0; k < 16; ++k) T[k] = fmaf(wj, sB[j * 16 + k], T[k]);
    }

    #pragma unroll
    for (int ii = 0; ii < 3; ++ii) {
        float v = T[4 * ii + 3];
        v = fmaf(T[4 * ii + 0], px, v);
        v = fmaf(T[4 * ii + 1], py, v);
        v = fmaf(T[4 * ii + 2], pz, v);
        out[3 * pid + ii] = v;
    }

    const float4 q = *reinterpret_cast<const float4*>(rot + 4 * pid);
    float qn = rsqrtf(q.x * q.x + q.y * q.y + q.z * q.z + q.w * q.w);
    float qr = q.x * qn, qx = q.y * qn, qy = q.z * qn, qz = q.w * qn;

    float R[3][3];
    R[0][0] = 1.0f - 2.0f * (qy * qy + qz * qz);
    R[0][1] = 2.0f * (qx * qy - qr * qz);
    R[0][2] = 2.0f * (qx * qz + qr * qy);
    R[1][0] = 2.0f * (qx * qy + qr * qz);
    R[1][1] = 1.0f - 2.0f * (qx * qx + qz * qz);
    R[1][2] = 2.0f * (qy * qz - qr * qx);
    R[2][0] = 2.0f * (qx * qz - qr * qy);
    R[2][1] = 2.0f * (qy * qz + qr * qx);
    R[2][2] = 1.0f - 2.0f * (qx * qx + qy * qy);

    float* out_R = out + (size_t)3 * n;
    #pragma unroll
    for (int ii = 0; ii < 3; ++ii) {
        #pragma unroll
        for (int k = 0; k < 3; ++k) {
            float v = T[4 * ii + 0] * R[0][k];
            v = fmaf(T[4 * ii + 1], R[1][k], v);
            v = fmaf(T[4 * ii + 2], R[2][k], v);
            out_R[9 * pid + 3 * ii + k] = v;
        }
    }

    float4* out_T = reinterpret_cast<float4*>(out + (size_t)12 * n) + (size_t)4 * pid;
    #pragma unroll
    for (int k = 0; k < 4; ++k)
        out_T[k] = make_float4(T[4 * k + 0], T[4 * k + 1], T[4 * k + 2], T[4 * k + 3]);
}

extern "C" void kernel_launch(void* const* d_in, const int* in_sizes, int n_in,
                              void* d_out, int out_size)
{
    const float* xyz   = (const float*)d_in[0];
    const float* rot   = (const float*)d_in[1];
    const float* verts = (const float*)d_in[2];
    const float* W     = (const float*)d_in[3];
    const float* bones = (const float*)d_in[4];
    float* out = (float*)d_out;

    const int n  = in_sizes[0] / 3;   // 100000
    const int nv = in_sizes[2] / 3;   // 6890
    const int mx = (n > nv) ? n : nv;

    cudaFuncSetAttribute(nn_kernel,
                         cudaFuncAttributeMaxDynamicSharedMemorySize, SMEM_TOT);

    zero_counts<<<NCELLS / 256, 256>>>(nv);
    count_kernel<<<(mx + 255) / 256, 256>>>(verts, xyz, nv, n);
    scan_offsets<<<2, 1024>>>();
    scatter_kernel<<<(mx + 255) / 256, 256>>>(verts, nv, n);
    bounds_kernel<<<1, 1024>>>(nv);
    nn_kernel<<<(n + NTHR - 1) / NTHR, NTHR, SMEM_TOT>>>(xyz, rot, W, bones, out, n, nv);
}